// round 1
// baseline (speedup 1.0000x reference)
#include <cuda_runtime.h>
#include <math.h>

// ---------------------------------------------------------------------------
// Problem constants
// ---------------------------------------------------------------------------
#define NCH        32            // C_FEAT
#define R_RAYS     8192
#define S_SAMP     64
#define NPTS       (R_RAYS * S_SAMP)   // 524288
#define TILE       128

// hi planes: [spatial][32], spatial offsets per plane (H=2h, W=2w)
//   p0:128x128  p1:128x128  p2:128x100  p3:128x128  p4:128x100  p5:128x100
#define HI_TOTAL   87552
// lo planes stored at quarter res: [h*w][32]
#define LO_TOTAL   21888

__device__ float g_hi[HI_TOTAL * NCH];     // ~11.2 MB
__device__ float g_lo[LO_TOTAL * NCH];     // ~2.8 MB
__device__ float g_encW[R_RAYS * 64];      // 2 MB: sh16(dir) @ Wc1[0:16,:]

// ---------------------------------------------------------------------------
// Kernel 1: build hi (full-res IDWT) and lo (0.5*yl, quarter res) planes
//   layout: hi[(soff + y*W + x)*32 + c], lo[(loff + i*w + j)*32 + c]
// ---------------------------------------------------------------------------
__global__ void build_planes(
    const float* __restrict__ yl0, const float* __restrict__ yh0,
    const float* __restrict__ yl1, const float* __restrict__ yh1,
    const float* __restrict__ yl2, const float* __restrict__ yh2,
    const float* __restrict__ yl3, const float* __restrict__ yh3,
    const float* __restrict__ yl4, const float* __restrict__ yh4,
    const float* __restrict__ yl5, const float* __restrict__ yh5)
{
    const int p    = blockIdx.y;
    const int c    = threadIdx.x & 31;
    const int pos  = blockIdx.x * (blockDim.x >> 5) + (threadIdx.x >> 5);

    int h, w, soff, loff;
    const float* yl;
    const float* yh;
    switch (p) {
        case 0: h=64; w=64; soff=0;     loff=0;     yl=yl0; yh=yh0; break;
        case 1: h=64; w=64; soff=16384; loff=4096;  yl=yl1; yh=yh1; break;
        case 2: h=64; w=50; soff=32768; loff=8192;  yl=yl2; yh=yh2; break;
        case 3: h=64; w=64; soff=45568; loff=11392; yl=yl3; yh=yh3; break;
        case 4: h=64; w=50; soff=61952; loff=15488; yl=yl4; yh=yh4; break;
        default:h=64; w=50; soff=74752; loff=18688; yl=yl5; yh=yh5; break;
    }
    const int W = 2 * w, H = 2 * h;
    if (pos >= H * W) return;

    const int y  = pos / W;
    const int x  = pos - y * W;
    const int i  = y >> 1, j = x >> 1;
    const int rr = y & 1,  ss = x & 1;
    const int hw = h * w;

    const float a = yl[c * hw + i * w + j];
    const float* b = yh + (c * 3) * hw + i * w + j;
    const float lh = b[0];
    const float hl = b[hw];
    const float hh = b[2 * hw];

    const float t1 = rr ? -lh : lh;                // row parity flips lh
    const float t2 = ss ? -hl : hl;                // col parity flips hl
    const float t3 = (rr ^ ss) ? -hh : hh;         // hh sign = product

    g_hi[(soff + pos) * NCH + c] = 0.5f * (a + t1 + t2 + t3);
    if (!rr && !ss)
        g_lo[(loff + i * w + j) * NCH + c] = 0.5f * a;
}

// ---------------------------------------------------------------------------
// Kernel 2: per-ray SH16 encoding @ Wc1[0:16,:]  -> g_encW[r][64]
// ---------------------------------------------------------------------------
__global__ void ray_enc(const float* __restrict__ dirs,
                        const float* __restrict__ Wc1)
{
    const int r = blockIdx.x;
    const int o = threadIdx.x;           // 64 outputs

    float x = dirs[3 * r], y = dirs[3 * r + 1], z = dirs[3 * r + 2];
    const float inv = 1.0f / sqrtf(x * x + y * y + z * z);
    x *= inv; y *= inv; z *= inv;
    const float xx = x * x, yy = y * y, zz = z * z;

    float sh[16];
    sh[0]  = 0.28209479177387814f;
    sh[1]  = -0.4886025119029199f * y;
    sh[2]  =  0.4886025119029199f * z;
    sh[3]  = -0.4886025119029199f * x;
    sh[4]  =  1.0925484305920792f * x * y;
    sh[5]  = -1.0925484305920792f * y * z;
    sh[6]  =  0.31539156525252005f * (3.0f * zz - 1.0f);
    sh[7]  = -1.0925484305920792f * x * z;
    sh[8]  =  0.5462742152960396f * (xx - yy);
    sh[9]  = -0.5900435899266435f * y * (3.0f * xx - yy);
    sh[10] =  2.890611442640554f * x * y * z;
    sh[11] = -0.4570457994644658f * y * (5.0f * zz - 1.0f);
    sh[12] =  0.3731763325901154f * z * (5.0f * zz - 3.0f);
    sh[13] = -0.4570457994644658f * x * (5.0f * zz - 1.0f);
    sh[14] =  1.445305721320277f * z * (xx - yy);
    sh[15] = -0.5900435899266435f * x * (xx - 3.0f * yy);

    float acc = 0.0f;
#pragma unroll
    for (int m = 0; m < 16; m++) acc += sh[m] * Wc1[m * 64 + o];
    g_encW[r * 64 + o] = acc;
}

// ---------------------------------------------------------------------------
// Kernel 3: fused gather + MLPs
// ---------------------------------------------------------------------------
// bilinear sample of hi (full res) and lo (quarter res) planes; lane = channel
#define SAMPLE(CY, CX, HH, WW, SOFF, LOFF)                                     \
    {                                                                          \
        const float yf = (CY + 1.0f) * 0.5f * (float)(HH - 1);                 \
        const float xf = (CX + 1.0f) * 0.5f * (float)(WW - 1);                 \
        int y0 = (int)floorf(yf);                                              \
        y0 = y0 < 0 ? 0 : (y0 > (HH - 1) ? (HH - 1) : y0);                     \
        int x0 = (int)floorf(xf);                                              \
        x0 = x0 < 0 ? 0 : (x0 > (WW - 1) ? (WW - 1) : x0);                     \
        const int y1 = (y0 + 1 > HH - 1) ? (HH - 1) : y0 + 1;                  \
        const int x1 = (x0 + 1 > WW - 1) ? (WW - 1) : x0 + 1;                  \
        float wy = yf - (float)y0; wy = wy < 0.f ? 0.f : (wy > 1.f ? 1.f : wy);\
        float wx = xf - (float)x0; wx = wx < 0.f ? 0.f : (wx > 1.f ? 1.f : wx);\
        const float* Hp = g_hi + (size_t)(SOFF) * NCH + lane;                  \
        const float h00 = Hp[(y0 * WW + x0) * NCH];                            \
        const float h01 = Hp[(y0 * WW + x1) * NCH];                            \
        const float h10 = Hp[(y1 * WW + x0) * NCH];                            \
        const float h11 = Hp[(y1 * WW + x1) * NCH];                            \
        const float a0 = h00 + wx * (h01 - h00);                               \
        const float a1 = h10 + wx * (h11 - h10);                               \
        fh *= (a0 + wy * (a1 - a0));                                           \
        const int i0 = y0 >> 1, i1 = y1 >> 1;                                  \
        const int j0 = x0 >> 1, j1 = x1 >> 1;                                  \
        const int w2 = (WW) >> 1;                                              \
        const float* Lp = g_lo + (size_t)(LOFF) * NCH + lane;                  \
        const float l00 = Lp[(i0 * w2 + j0) * NCH];                            \
        const float l01 = Lp[(i0 * w2 + j1) * NCH];                            \
        const float l10 = Lp[(i1 * w2 + j0) * NCH];                            \
        const float l11 = Lp[(i1 * w2 + j1) * NCH];                            \
        const float b0 = l00 + wx * (l01 - l00);                               \
        const float b1 = l10 + wx * (l11 - l10);                               \
        fl *= (b0 + wy * (b1 - b0));                                           \
    }

// dynamic smem layout (floats):
//   sW1 4096 | sW2 1024 | sWg 960 | sC2 4096 | sC3 256 | sEnc 128 | sF 128*65
#define SMEM_FLOATS (4096 + 1024 + 960 + 4096 + 256 + 128 + TILE * 65)
#define SMEM_BYTES  (SMEM_FLOATS * 4)

extern "C" __global__ void __launch_bounds__(TILE)
wave_main(const float* __restrict__ pts, const float* __restrict__ ts,
          const float* __restrict__ Wsig1, const float* __restrict__ Wsig2,
          const float* __restrict__ Wc1, const float* __restrict__ Wc2,
          const float* __restrict__ Wc3, float* __restrict__ out)
{
    extern __shared__ float smem[];
    float* sW1  = smem;                 // Wsig1 [64][64]
    float* sW2  = sW1 + 4096;           // Wsig2 [64][16]
    float* sWg  = sW2 + 1024;           // Wc1 rows 16..30 [15][64]
    float* sC2  = sWg + 960;            // Wc2 [64][64]
    float* sC3  = sC2 + 4096;           // Wc3 padded [64][4]
    float* sEnc = sC3 + 256;            // encW for the block's 2 rays [2][64]
    float* sF   = sEnc + 128;           // feats [128][65] (padded)

    const int tid  = threadIdx.x;
    const int base = blockIdx.x * TILE;

    for (int idx = tid; idx < 4096; idx += TILE) sW1[idx] = Wsig1[idx];
    for (int idx = tid; idx < 1024; idx += TILE) sW2[idx] = Wsig2[idx];
    for (int idx = tid; idx < 960;  idx += TILE) sWg[idx] = Wc1[1024 + idx];
    for (int idx = tid; idx < 4096; idx += TILE) sC2[idx] = Wc2[idx];
    if (tid < 64) {
        sC3[tid * 4 + 0] = Wc3[tid * 3 + 0];
        sC3[tid * 4 + 1] = Wc3[tid * 3 + 1];
        sC3[tid * 4 + 2] = Wc3[tid * 3 + 2];
        sC3[tid * 4 + 3] = 0.0f;
    }
    // rays r0 = base/64, r0+1; their encW occupy g_encW[base .. base+127]
    sEnc[tid] = g_encW[base + tid];
    __syncthreads();

    // ---------------- phase A: warp-cooperative gather (lane = channel) ----
    const int wid  = tid >> 5;
    const int lane = tid & 31;
#pragma unroll 1
    for (int q = 0; q < 32; q++) {
        const int pl = wid * 32 + q;
        const int n  = base + pl;
        const float px = __ldg(pts + 3 * n);
        const float py = __ldg(pts + 3 * n + 1);
        const float pz = __ldg(pts + 3 * n + 2);
        const float tt = 2.0f * __ldg(ts + (n >> 6)) - 1.0f;

        float fh = 1.0f, fl = 1.0f;
        SAMPLE(px, py, 128, 128, 0,     0)      // combo (0,1)
        SAMPLE(px, pz, 128, 128, 16384, 4096)   // combo (0,2)
        SAMPLE(px, tt, 128, 100, 32768, 8192)   // combo (0,3)
        SAMPLE(py, pz, 128, 128, 45568, 11392)  // combo (1,2)
        SAMPLE(py, tt, 128, 100, 61952, 15488)  // combo (1,3)
        SAMPLE(pz, tt, 128, 100, 74752, 18688)  // combo (2,3)

        sF[pl * 65 + lane]      = fh;
        sF[pl * 65 + 32 + lane] = fl;
    }
    __syncthreads();

    // ---------------- phase B: thread-per-point MLPs -----------------------
    const int n = base + tid;

    // h1 = relu(feats @ Wsig1)
    float h1[64];
#pragma unroll
    for (int o = 0; o < 64; o++) h1[o] = 0.0f;
#pragma unroll 4
    for (int i = 0; i < 64; i++) {
        const float f = sF[tid * 65 + i];
#pragma unroll
        for (int o = 0; o < 64; o += 4) {
            const float4 wv = *(const float4*)&sW1[i * 64 + o];
            h1[o + 0] += f * wv.x;
            h1[o + 1] += f * wv.y;
            h1[o + 2] += f * wv.z;
            h1[o + 3] += f * wv.w;
        }
    }
#pragma unroll
    for (int o = 0; o < 64; o++) h1[o] = fmaxf(h1[o], 0.0f);

    // g = h1 @ Wsig2   (g[0:15]=geo, g[15]=log-density)
    float g[16];
#pragma unroll
    for (int o = 0; o < 16; o++) g[o] = 0.0f;
#pragma unroll 8
    for (int i = 0; i < 64; i++) {
        const float f = h1[i];
#pragma unroll
        for (int o = 0; o < 16; o += 4) {
            const float4 wv = *(const float4*)&sW2[i * 16 + o];
            g[o + 0] += f * wv.x;
            g[o + 1] += f * wv.y;
            g[o + 2] += f * wv.z;
            g[o + 3] += f * wv.w;
        }
    }
    float dlog = g[15];
    dlog = dlog < -15.0f ? -15.0f : (dlog > 15.0f ? 15.0f : dlog);
    const float density = expf(dlog);

    // h2 = relu(encW + geo @ Wc1[16:31,:])
    const int rl = (tid >> 6);   // 0/1: which of the block's two rays
    float h2[64];
#pragma unroll
    for (int o = 0; o < 64; o++) h2[o] = sEnc[rl * 64 + o];
#pragma unroll
    for (int m = 0; m < 15; m++) {
        const float f = g[m];
#pragma unroll
        for (int o = 0; o < 64; o += 4) {
            const float4 wv = *(const float4*)&sWg[m * 64 + o];
            h2[o + 0] += f * wv.x;
            h2[o + 1] += f * wv.y;
            h2[o + 2] += f * wv.z;
            h2[o + 3] += f * wv.w;
        }
    }
#pragma unroll
    for (int o = 0; o < 64; o++) h2[o] = fmaxf(h2[o], 0.0f);

    // h3 = relu(h2 @ Wc2)
    float h3[64];
#pragma unroll
    for (int o = 0; o < 64; o++) h3[o] = 0.0f;
#pragma unroll 4
    for (int i = 0; i < 64; i++) {
        const float f = h2[i];
#pragma unroll
        for (int o = 0; o < 64; o += 4) {
            const float4 wv = *(const float4*)&sC2[i * 64 + o];
            h3[o + 0] += f * wv.x;
            h3[o + 1] += f * wv.y;
            h3[o + 2] += f * wv.z;
            h3[o + 3] += f * wv.w;
        }
    }

    // rgb = sigmoid(h3 @ Wc3)
    float r0 = 0.0f, r1 = 0.0f, r2 = 0.0f;
#pragma unroll 8
    for (int i = 0; i < 64; i++) {
        const float f = fmaxf(h3[i], 0.0f);
        const float4 wv = *(const float4*)&sC3[i * 4];
        r0 += f * wv.x;
        r1 += f * wv.y;
        r2 += f * wv.z;
    }
    float4 res;
    res.x = 1.0f / (1.0f + expf(-r0));
    res.y = 1.0f / (1.0f + expf(-r1));
    res.z = 1.0f / (1.0f + expf(-r2));
    res.w = density;
    ((float4*)out)[n] = res;
}

// ---------------------------------------------------------------------------
// kernel_launch
// ---------------------------------------------------------------------------
extern "C" void kernel_launch(void* const* d_in, const int* in_sizes, int n_in,
                              void* d_out, int out_size)
{
    const float* pts  = (const float*)d_in[0];
    const float* dirs = (const float*)d_in[1];
    const float* ts   = (const float*)d_in[2];
    const float* yl0 = (const float*)d_in[3];
    const float* yh0 = (const float*)d_in[4];
    const float* yl1 = (const float*)d_in[5];
    const float* yh1 = (const float*)d_in[6];
    const float* yl2 = (const float*)d_in[7];
    const float* yh2 = (const float*)d_in[8];
    const float* yl3 = (const float*)d_in[9];
    const float* yh3 = (const float*)d_in[10];
    const float* yl4 = (const float*)d_in[11];
    const float* yh4 = (const float*)d_in[12];
    const float* yl5 = (const float*)d_in[13];
    const float* yh5 = (const float*)d_in[14];
    const float* Wsig1 = (const float*)d_in[15];
    const float* Wsig2 = (const float*)d_in[16];
    const float* Wc1   = (const float*)d_in[17];
    const float* Wc2   = (const float*)d_in[18];
    const float* Wc3   = (const float*)d_in[19];

    cudaFuncSetAttribute(wave_main,
                         cudaFuncAttributeMaxDynamicSharedMemorySize,
                         SMEM_BYTES);

    // 1) build hi/lo planes (32 positions x 32 channels per block)
    dim3 gridB(512, 6);
    build_planes<<<gridB, 1024>>>(yl0, yh0, yl1, yh1, yl2, yh2,
                                  yl3, yh3, yl4, yh4, yl5, yh5);

    // 2) per-ray SH encoding premultiplied into Wc1[0:16,:]
    ray_enc<<<R_RAYS, 64>>>(dirs, Wc1);

    // 3) fused gather + MLPs
    wave_main<<<NPTS / TILE, TILE, SMEM_BYTES>>>(
        pts, ts, Wsig1, Wsig2, Wc1, Wc2, Wc3, (float*)d_out);
}

// round 2
// speedup vs baseline: 1.2848x; 1.2848x over previous
#include <cuda_runtime.h>
#include <math.h>

// ---------------------------------------------------------------------------
// Problem constants
// ---------------------------------------------------------------------------
#define NCH        32            // C_FEAT
#define R_RAYS     8192
#define S_SAMP     64
#define NPTS       (R_RAYS * S_SAMP)   // 524288
#define TILE       128

// hi planes: [spatial][32], spatial offsets per plane (H=2h, W=2w)
//   p0:128x128  p1:128x128  p2:128x100  p3:128x128  p4:128x100  p5:128x100
#define HI_TOTAL   87552
// lo planes stored at quarter res: [h*w][32]
#define LO_TOTAL   21888

__device__ float g_hi[HI_TOTAL * NCH];     // ~11.2 MB
__device__ float g_lo[LO_TOTAL * NCH];     // ~2.8 MB
__device__ float g_encW[R_RAYS * 64];      // 2 MB: sh16(dir) @ Wc1[0:16,:]

// ---------------------------------------------------------------------------
// packed f32x2 helpers (Blackwell sm_100+)
// ---------------------------------------------------------------------------
__device__ __forceinline__ unsigned long long pack2(float a, float b) {
    unsigned long long r;
    asm("mov.b64 %0, {%1, %2};" : "=l"(r) : "f"(a), "f"(b));
    return r;
}
__device__ __forceinline__ void unpack2(unsigned long long v, float& a, float& b) {
    asm("mov.b64 {%0, %1}, %2;" : "=f"(a), "=f"(b) : "l"(v));
}
__device__ __forceinline__ unsigned long long ffma2(unsigned long long a,
                                                    unsigned long long b,
                                                    unsigned long long c) {
    unsigned long long d;
    asm("fma.rn.f32x2 %0, %1, %2, %3;" : "=l"(d) : "l"(a), "l"(b), "l"(c));
    return d;
}

// ---------------------------------------------------------------------------
// Kernel 1: build hi (full-res IDWT) and lo (0.5*yl, quarter res) planes.
// One thread per INPUT coefficient (c, i, j): 4 loads -> 4 output pixels
// (stores coalesced across lanes since lane = channel), plus the lo store.
// ---------------------------------------------------------------------------
__global__ void build_planes(
    const float* __restrict__ yl0, const float* __restrict__ yh0,
    const float* __restrict__ yl1, const float* __restrict__ yh1,
    const float* __restrict__ yl2, const float* __restrict__ yh2,
    const float* __restrict__ yl3, const float* __restrict__ yh3,
    const float* __restrict__ yl4, const float* __restrict__ yh4,
    const float* __restrict__ yl5, const float* __restrict__ yh5)
{
    const int p    = blockIdx.y;
    const int c    = threadIdx.x & 31;
    const int pos  = blockIdx.x * (blockDim.x >> 5) + (threadIdx.x >> 5); // input idx

    int h, w, soff, loff;
    const float* yl;
    const float* yh;
    switch (p) {
        case 0: h=64; w=64; soff=0;     loff=0;     yl=yl0; yh=yh0; break;
        case 1: h=64; w=64; soff=16384; loff=4096;  yl=yl1; yh=yh1; break;
        case 2: h=64; w=50; soff=32768; loff=8192;  yl=yl2; yh=yh2; break;
        case 3: h=64; w=64; soff=45568; loff=11392; yl=yl3; yh=yh3; break;
        case 4: h=64; w=50; soff=61952; loff=15488; yl=yl4; yh=yh4; break;
        default:h=64; w=50; soff=74752; loff=18688; yl=yl5; yh=yh5; break;
    }
    const int hw = h * w;
    if (pos >= hw) return;

    const int i = pos / w;
    const int j = pos - i * w;
    const int W = 2 * w;

    const float a  = __ldg(yl + c * hw + pos);
    const float* b = yh + (c * 3) * hw + pos;
    const float lh = __ldg(b);
    const float hl = __ldg(b + hw);
    const float hh = __ldg(b + 2 * hw);

    const float ee = 0.5f * (a + lh + hl + hh);
    const float eo = 0.5f * (a + lh - hl - hh);
    const float oe = 0.5f * (a - lh + hl - hh);
    const float oo = 0.5f * (a - lh - hl + hh);

    float* dst = g_hi + (size_t)(soff + (2 * i) * W + 2 * j) * NCH + c;
    dst[0]            = ee;
    dst[NCH]          = eo;
    dst[W * NCH]      = oe;
    dst[W * NCH + NCH] = oo;

    g_lo[(size_t)(loff + pos) * NCH + c] = 0.5f * a;
}

// ---------------------------------------------------------------------------
// Kernel 2: per-ray SH16 encoding @ Wc1[0:16,:]  -> g_encW[r][64]
// ---------------------------------------------------------------------------
__global__ void ray_enc(const float* __restrict__ dirs,
                        const float* __restrict__ Wc1)
{
    const int r = blockIdx.x;
    const int o = threadIdx.x;           // 64 outputs

    float x = dirs[3 * r], y = dirs[3 * r + 1], z = dirs[3 * r + 2];
    const float inv = 1.0f / sqrtf(x * x + y * y + z * z);
    x *= inv; y *= inv; z *= inv;
    const float xx = x * x, yy = y * y, zz = z * z;

    float sh[16];
    sh[0]  = 0.28209479177387814f;
    sh[1]  = -0.4886025119029199f * y;
    sh[2]  =  0.4886025119029199f * z;
    sh[3]  = -0.4886025119029199f * x;
    sh[4]  =  1.0925484305920792f * x * y;
    sh[5]  = -1.0925484305920792f * y * z;
    sh[6]  =  0.31539156525252005f * (3.0f * zz - 1.0f);
    sh[7]  = -1.0925484305920792f * x * z;
    sh[8]  =  0.5462742152960396f * (xx - yy);
    sh[9]  = -0.5900435899266435f * y * (3.0f * xx - yy);
    sh[10] =  2.890611442640554f * x * y * z;
    sh[11] = -0.4570457994644658f * y * (5.0f * zz - 1.0f);
    sh[12] =  0.3731763325901154f * z * (5.0f * zz - 3.0f);
    sh[13] = -0.4570457994644658f * x * (5.0f * zz - 1.0f);
    sh[14] =  1.445305721320277f * z * (xx - yy);
    sh[15] = -0.5900435899266435f * x * (xx - 3.0f * yy);

    float acc = 0.0f;
#pragma unroll
    for (int m = 0; m < 16; m++) acc += sh[m] * Wc1[m * 64 + o];
    g_encW[r * 64 + o] = acc;
}

// ---------------------------------------------------------------------------
// Kernel 3: fused gather + MLPs
// ---------------------------------------------------------------------------
#define SAMPLE(CY, CX, HH, WW, SOFF, LOFF)                                     \
    {                                                                          \
        const float yf = (CY + 1.0f) * 0.5f * (float)(HH - 1);                 \
        const float xf = (CX + 1.0f) * 0.5f * (float)(WW - 1);                 \
        int y0 = (int)floorf(yf);                                              \
        y0 = y0 < 0 ? 0 : (y0 > (HH - 1) ? (HH - 1) : y0);                     \
        int x0 = (int)floorf(xf);                                              \
        x0 = x0 < 0 ? 0 : (x0 > (WW - 1) ? (WW - 1) : x0);                     \
        const int y1 = (y0 + 1 > HH - 1) ? (HH - 1) : y0 + 1;                  \
        const int x1 = (x0 + 1 > WW - 1) ? (WW - 1) : x0 + 1;                  \
        float wy = yf - (float)y0; wy = wy < 0.f ? 0.f : (wy > 1.f ? 1.f : wy);\
        float wx = xf - (float)x0; wx = wx < 0.f ? 0.f : (wx > 1.f ? 1.f : wx);\
        const float* Hp = g_hi + (size_t)(SOFF) * NCH + lane;                  \
        const float h00 = Hp[(y0 * WW + x0) * NCH];                            \
        const float h01 = Hp[(y0 * WW + x1) * NCH];                            \
        const float h10 = Hp[(y1 * WW + x0) * NCH];                            \
        const float h11 = Hp[(y1 * WW + x1) * NCH];                            \
        const float a0 = h00 + wx * (h01 - h00);                               \
        const float a1 = h10 + wx * (h11 - h10);                               \
        fh *= (a0 + wy * (a1 - a0));                                           \
        const int i0 = y0 >> 1, i1 = y1 >> 1;                                  \
        const int j0 = x0 >> 1, j1 = x1 >> 1;                                  \
        const int w2 = (WW) >> 1;                                              \
        const float* Lp = g_lo + (size_t)(LOFF) * NCH + lane;                  \
        const float l00 = Lp[(i0 * w2 + j0) * NCH];                            \
        const float l01 = Lp[(i0 * w2 + j1) * NCH];                            \
        const float l10 = Lp[(i1 * w2 + j0) * NCH];                            \
        const float l11 = Lp[(i1 * w2 + j1) * NCH];                            \
        const float b0 = l00 + wx * (l01 - l00);                               \
        const float b1 = l10 + wx * (l11 - l10);                               \
        fl *= (b0 + wy * (b1 - b0));                                           \
    }

// dynamic smem layout (floats):
//   sW1 4096 | sW2 1024 | sWg 960 | sC2 4096 | sC3 256 | sEnc 128 | sF 128*65
#define SMEM_FLOATS (4096 + 1024 + 960 + 4096 + 256 + 128 + TILE * 65)
#define SMEM_BYTES  (SMEM_FLOATS * 4)

extern "C" __global__ void __launch_bounds__(TILE)
wave_main(const float* __restrict__ pts, const float* __restrict__ ts,
          const float* __restrict__ Wsig1, const float* __restrict__ Wsig2,
          const float* __restrict__ Wc1, const float* __restrict__ Wc2,
          const float* __restrict__ Wc3, float* __restrict__ out)
{
    extern __shared__ float smem[];
    float* sW1  = smem;                 // Wsig1 [64][64]
    float* sW2  = sW1 + 4096;           // Wsig2 [64][16]
    float* sWg  = sW2 + 1024;           // Wc1 rows 16..30 [15][64]
    float* sC2  = sWg + 960;            // Wc2 [64][64]
    float* sC3  = sC2 + 4096;           // Wc3 padded [64][4]
    float* sEnc = sC3 + 256;            // encW for the block's 2 rays [2][64]
    float* sF   = sEnc + 128;           // feats [128][65] (padded)

    const int tid  = threadIdx.x;
    const int base = blockIdx.x * TILE;

    for (int idx = tid; idx < 4096; idx += TILE) sW1[idx] = Wsig1[idx];
    for (int idx = tid; idx < 1024; idx += TILE) sW2[idx] = Wsig2[idx];
    for (int idx = tid; idx < 960;  idx += TILE) sWg[idx] = Wc1[1024 + idx];
    for (int idx = tid; idx < 4096; idx += TILE) sC2[idx] = Wc2[idx];
    if (tid < 64) {
        sC3[tid * 4 + 0] = Wc3[tid * 3 + 0];
        sC3[tid * 4 + 1] = Wc3[tid * 3 + 1];
        sC3[tid * 4 + 2] = Wc3[tid * 3 + 2];
        sC3[tid * 4 + 3] = 0.0f;
    }
    sEnc[tid] = g_encW[base + tid];
    __syncthreads();

    // ---------------- phase A: warp-cooperative gather (lane = channel) ----
    const int wid  = tid >> 5;
    const int lane = tid & 31;
#pragma unroll 1
    for (int q = 0; q < 32; q++) {
        const int pl = wid * 32 + q;
        const int n  = base + pl;
        const float px = __ldg(pts + 3 * n);
        const float py = __ldg(pts + 3 * n + 1);
        const float pz = __ldg(pts + 3 * n + 2);
        const float tt = 2.0f * __ldg(ts + (n >> 6)) - 1.0f;

        float fh = 1.0f, fl = 1.0f;
        SAMPLE(px, py, 128, 128, 0,     0)      // combo (0,1)
        SAMPLE(px, pz, 128, 128, 16384, 4096)   // combo (0,2)
        SAMPLE(px, tt, 128, 100, 32768, 8192)   // combo (0,3)
        SAMPLE(py, pz, 128, 128, 45568, 11392)  // combo (1,2)
        SAMPLE(py, tt, 128, 100, 61952, 15488)  // combo (1,3)
        SAMPLE(pz, tt, 128, 100, 74752, 18688)  // combo (2,3)

        sF[pl * 65 + lane]      = fh;
        sF[pl * 65 + 32 + lane] = fl;
    }
    __syncthreads();

    // ---------------- phase B: thread-per-point MLPs (packed f32x2) --------
    const int n = base + tid;

    // h1 = relu(feats @ Wsig1)
    unsigned long long h1p[32];
#pragma unroll
    for (int o = 0; o < 32; o++) h1p[o] = 0ULL;
#pragma unroll 4
    for (int i = 0; i < 64; i++) {
        const float f = sF[tid * 65 + i];
        const unsigned long long fp = pack2(f, f);
#pragma unroll
        for (int o2 = 0; o2 < 32; o2 += 2) {
            const ulonglong2 wv = *(const ulonglong2*)&sW1[i * 64 + o2 * 2];
            h1p[o2 + 0] = ffma2(fp, wv.x, h1p[o2 + 0]);
            h1p[o2 + 1] = ffma2(fp, wv.y, h1p[o2 + 1]);
        }
    }
    float h1[64];
#pragma unroll
    for (int o2 = 0; o2 < 32; o2++) {
        float a, b;
        unpack2(h1p[o2], a, b);
        h1[2 * o2]     = fmaxf(a, 0.0f);
        h1[2 * o2 + 1] = fmaxf(b, 0.0f);
    }

    // g = h1 @ Wsig2   (g[0:15]=geo, g[15]=log-density)
    unsigned long long gp[8];
#pragma unroll
    for (int o = 0; o < 8; o++) gp[o] = 0ULL;
#pragma unroll 8
    for (int i = 0; i < 64; i++) {
        const unsigned long long fp = pack2(h1[i], h1[i]);
#pragma unroll
        for (int o2 = 0; o2 < 8; o2 += 2) {
            const ulonglong2 wv = *(const ulonglong2*)&sW2[i * 16 + o2 * 2];
            gp[o2 + 0] = ffma2(fp, wv.x, gp[o2 + 0]);
            gp[o2 + 1] = ffma2(fp, wv.y, gp[o2 + 1]);
        }
    }
    float g[16];
#pragma unroll
    for (int o2 = 0; o2 < 8; o2++) unpack2(gp[o2], g[2 * o2], g[2 * o2 + 1]);

    float dlog = g[15];
    dlog = dlog < -15.0f ? -15.0f : (dlog > 15.0f ? 15.0f : dlog);
    const float density = expf(dlog);

    // h2 = relu(encW + geo @ Wc1[16:31,:])
    const int rl = (tid >> 6);
    unsigned long long h2p[32];
#pragma unroll
    for (int o2 = 0; o2 < 32; o2++)
        h2p[o2] = *(const unsigned long long*)&sEnc[rl * 64 + 2 * o2];
#pragma unroll
    for (int m = 0; m < 15; m++) {
        const unsigned long long fp = pack2(g[m], g[m]);
#pragma unroll
        for (int o2 = 0; o2 < 32; o2 += 2) {
            const ulonglong2 wv = *(const ulonglong2*)&sWg[m * 64 + o2 * 2];
            h2p[o2 + 0] = ffma2(fp, wv.x, h2p[o2 + 0]);
            h2p[o2 + 1] = ffma2(fp, wv.y, h2p[o2 + 1]);
        }
    }
    float h2[64];
#pragma unroll
    for (int o2 = 0; o2 < 32; o2++) {
        float a, b;
        unpack2(h2p[o2], a, b);
        h2[2 * o2]     = fmaxf(a, 0.0f);
        h2[2 * o2 + 1] = fmaxf(b, 0.0f);
    }

    // h3 = relu(h2 @ Wc2)
    unsigned long long h3p[32];
#pragma unroll
    for (int o = 0; o < 32; o++) h3p[o] = 0ULL;
#pragma unroll 4
    for (int i = 0; i < 64; i++) {
        const unsigned long long fp = pack2(h2[i], h2[i]);
#pragma unroll
        for (int o2 = 0; o2 < 32; o2 += 2) {
            const ulonglong2 wv = *(const ulonglong2*)&sC2[i * 64 + o2 * 2];
            h3p[o2 + 0] = ffma2(fp, wv.x, h3p[o2 + 0]);
            h3p[o2 + 1] = ffma2(fp, wv.y, h3p[o2 + 1]);
        }
    }

    // rgb = sigmoid(h3 @ Wc3)   (r0,r1 packed; r2 scalar)
    unsigned long long r01 = 0ULL;
    float r2 = 0.0f;
#pragma unroll 8
    for (int i2 = 0; i2 < 32; i2++) {
        float a, b;
        unpack2(h3p[i2], a, b);
        a = fmaxf(a, 0.0f);
        b = fmaxf(b, 0.0f);
        {
            const float4 wv = *(const float4*)&sC3[(2 * i2) * 4];
            r01 = ffma2(pack2(a, a), pack2(wv.x, wv.y), r01);
            r2 += a * wv.z;
        }
        {
            const float4 wv = *(const float4*)&sC3[(2 * i2 + 1) * 4];
            r01 = ffma2(pack2(b, b), pack2(wv.x, wv.y), r01);
            r2 += b * wv.z;
        }
    }
    float r0, r1;
    unpack2(r01, r0, r1);

    float4 res;
    res.x = 1.0f / (1.0f + expf(-r0));
    res.y = 1.0f / (1.0f + expf(-r1));
    res.z = 1.0f / (1.0f + expf(-r2));
    res.w = density;
    ((float4*)out)[n] = res;
}

// ---------------------------------------------------------------------------
// kernel_launch
// ---------------------------------------------------------------------------
extern "C" void kernel_launch(void* const* d_in, const int* in_sizes, int n_in,
                              void* d_out, int out_size)
{
    const float* pts  = (const float*)d_in[0];
    const float* dirs = (const float*)d_in[1];
    const float* ts   = (const float*)d_in[2];
    const float* yl0 = (const float*)d_in[3];
    const float* yh0 = (const float*)d_in[4];
    const float* yl1 = (const float*)d_in[5];
    const float* yh1 = (const float*)d_in[6];
    const float* yl2 = (const float*)d_in[7];
    const float* yh2 = (const float*)d_in[8];
    const float* yl3 = (const float*)d_in[9];
    const float* yh3 = (const float*)d_in[10];
    const float* yl4 = (const float*)d_in[11];
    const float* yh4 = (const float*)d_in[12];
    const float* yl5 = (const float*)d_in[13];
    const float* yh5 = (const float*)d_in[14];
    const float* Wsig1 = (const float*)d_in[15];
    const float* Wsig2 = (const float*)d_in[16];
    const float* Wc1   = (const float*)d_in[17];
    const float* Wc2   = (const float*)d_in[18];
    const float* Wc3   = (const float*)d_in[19];

    cudaFuncSetAttribute(wave_main,
                         cudaFuncAttributeMaxDynamicSharedMemorySize,
                         SMEM_BYTES);

    // 1) build hi/lo planes (one thread per input coeff; 32 coeffs/block-warp)
    dim3 gridB(128, 6);
    build_planes<<<gridB, 1024>>>(yl0, yh0, yl1, yh1, yl2, yh2,
                                  yl3, yh3, yl4, yh4, yl5, yh5);

    // 2) per-ray SH encoding premultiplied into Wc1[0:16,:]
    ray_enc<<<R_RAYS, 64>>>(dirs, Wc1);

    // 3) fused gather + MLPs
    wave_main<<<NPTS / TILE, TILE, SMEM_BYTES>>>(
        pts, ts, Wsig1, Wsig2, Wc1, Wc2, Wc3, (float*)d_out);
}